// round 14
// baseline (speedup 1.0000x reference)
#include <cuda_runtime.h>
#include <cuda_fp16.h>

#define BATCH   4
#define SEQ     4096
#define DMODEL  1024
#define HEAD    64
#define BT      (BATCH * SEQ)
#define TILE_BYTES 16384   // one 128x64 fp16 plane tile, SW128 swizzled

typedef unsigned int u32;
typedef unsigned short u16;

// fp16 operand planes (attention-ready swizzled tile layout)
__device__ u16 g_qf[BT * HEAD];            // q single fp16
__device__ u16 g_kf[BT * HEAD];            // k single fp16
__device__ u16 g_vf[BT * HEAD];            // v single fp16
// W single fp16 plane: chunk c tile = 192 n-rows x 64 k, 24KB, n-major SW128
__device__ u16 g_wf[16 * 192 * HEAD];
// split-K partials + per-row-block arrival counters (self-resetting)
__device__ float g_po[2][BT * HEAD];
__device__ float g_pl[2][BT];
__device__ int   g_flag[128];

// ============================ helpers ============================
__device__ __forceinline__ u32 smem_u32(const void* p) {
    u32 a;
    asm("{ .reg .u64 t; cvta.to.shared.u64 t, %1; cvt.u32.u64 %0, t; }" : "=r"(a) : "l"(p));
    return a;
}
__device__ __forceinline__ u32 sw128(u32 off) { return off ^ ((off >> 3) & 0x70); }

__device__ __forceinline__ void ldsm4(u32 a, u32& r0, u32& r1, u32& r2, u32& r3) {
    asm volatile("ldmatrix.sync.aligned.m8n8.x4.shared.b16 {%0,%1,%2,%3}, [%4];"
                 : "=r"(r0), "=r"(r1), "=r"(r2), "=r"(r3) : "r"(a));
}
__device__ __forceinline__ void ldsm4t(u32 a, u32& r0, u32& r1, u32& r2, u32& r3) {
    asm volatile("ldmatrix.sync.aligned.m8n8.x4.trans.shared.b16 {%0,%1,%2,%3}, [%4];"
                 : "=r"(r0), "=r"(r1), "=r"(r2), "=r"(r3) : "r"(a));
}
// fp16 mma m16n8k16, fp32 accumulate
__device__ __forceinline__ void mmah(float* d, u32 a0, u32 a1, u32 a2, u32 a3,
                                     u32 b0, u32 b1) {
    asm volatile(
        "mma.sync.aligned.m16n8k16.row.col.f32.f16.f16.f32 "
        "{%0,%1,%2,%3},{%4,%5,%6,%7},{%8,%9},{%0,%1,%2,%3};"
        : "+f"(d[0]), "+f"(d[1]), "+f"(d[2]), "+f"(d[3])
        : "r"(a0), "r"(a1), "r"(a2), "r"(a3), "r"(b0), "r"(b1));
}
__device__ __forceinline__ u32 packf16(float a, float b) {
    __half2 h = __floats2half2_rn(a, b);
    return *reinterpret_cast<u32*>(&h);
}
__device__ __forceinline__ u32 frag_addr(u32 base, int row0, int colb) {
    int lane = threadIdx.x & 31;
    int tile = lane >> 3, l7 = lane & 7;
    int row = row0 + l7 + ((tile & 1) << 3);
    int col = colb + ((tile >> 1) << 4);
    return base + sw128((u32)(row * 128 + col));
}
__device__ __forceinline__ void cpa16(u32 dst, const void* src) {
    asm volatile("cp.async.cg.shared.global [%0], [%1], 16;" :: "r"(dst), "l"(src));
}
__device__ __forceinline__ void cp_commit() {
    asm volatile("cp.async.commit_group;" ::: "memory");
}
__device__ __forceinline__ void copy_plane(u32 dst, const char* src, int t) {
    #pragma unroll
    for (int j = 0; j < 4; j++)
        cpa16(dst + (u32)(t * 16 + j * 4096), src + t * 16 + j * 4096);
}

// ============================ W prepass ============================
__global__ __launch_bounds__(256) void wprep_kernel(
    const float* __restrict__ Wq, const float* __restrict__ Wk,
    const float* __restrict__ Wv)
{
    const int sel = blockIdx.x >> 4, c = blockIdx.x & 15;
    const float* W = (sel == 0) ? Wq : (sel == 1) ? Wk : Wv;
    const int k0 = c * 64;
    char* tp = (char*)g_wf + (size_t)c * (192 * 128);
    const int t = threadIdx.x;
    #pragma unroll
    for (int j = 0; j < 8; j++) {
        int idx = t + j * 256;           // 2048 = 64 nl x 32 kq
        int kq = idx & 31, nl = idx >> 5;
        float w0 = W[(size_t)(k0 + 2 * kq)     * HEAD + nl];
        float w1 = W[(size_t)(k0 + 2 * kq + 1) * HEAD + nl];
        u32 off = sw128((u32)((sel * 64 + nl) * 128 + kq * 4));
        *(u32*)(tp + off) = packf16(w0, w1);
    }
}

// ============================ Projection kernel (R11 config) ============================
#define PJ_STAGE 40960
#define PJ_XH    (2 * PJ_STAGE)       // 81920, 8KB converted x plane
#define PJ_SMEM  (PJ_XH + 8192)       // 90112

__device__ __forceinline__ void pj_copy_stage(u32 smb, const float* x, int m0,
                                              int c, int t) {
    const u32 base = smb + (u32)(c & 1) * PJ_STAGE;
    const int k0 = c * 64;
    #pragma unroll
    for (int j = 0; j < 4; j++) {
        int i = t + j * 256;             // 1024 x 16B = 16KB
        int r = i >> 4, cq = i & 15;
        cpa16(base + (u32)(r * 256 + cq * 16),
              &x[(size_t)(m0 + r) * DMODEL + k0 + cq * 4]);
    }
    const char* wsrc = (const char*)g_wf + (size_t)c * (192 * 128);
    #pragma unroll
    for (int j = 0; j < 6; j++) {
        int i = t + j * 256;             // 1536 x 16B = 24KB
        cpa16(base + 16384u + (u32)(i * 16), wsrc + i * 16);
    }
    cp_commit();
}

__global__ __launch_bounds__(256) void proj_kernel(
    const float* __restrict__ bq, const float* __restrict__ bk,
    const float* __restrict__ bv, const float* __restrict__ x)
{
    extern __shared__ char sm[];
    const u32 smb = smem_u32(sm);
    const int t = threadIdx.x, w = t >> 5, lane = t & 31;
    const int g = lane >> 2, tg = lane & 3;
    const int m0 = blockIdx.x * 64;
    const int mq = w & 3, nh = w >> 2;
    const int mb = mq * 16;

    float acc[12][4];
    #pragma unroll
    for (int i = 0; i < 12; i++)
        #pragma unroll
        for (int e = 0; e < 4; e++) acc[i][e] = 0.0f;

    pj_copy_stage(smb, x, m0, 0, t);
    pj_copy_stage(smb, x, m0, 1, t);

    for (int c = 0; c < 16; c++) {
        if (c + 1 < 16) asm volatile("cp.async.wait_group 1;" ::: "memory");
        else            asm volatile("cp.async.wait_group 0;" ::: "memory");
        __syncthreads();

        const u32 sb = smb + (u32)(c & 1) * PJ_STAGE;
        // convert x chunk fp32 -> fp16 plane (64 rows x 64 k)
        #pragma unroll
        for (int j = 0; j < 8; j++) {
            int idx = t + j * 256;       // 2048 pairs
            int r = idx >> 5, kq = idx & 31;
            float2 v;
            asm volatile("ld.shared.v2.f32 {%0,%1}, [%2];"
                         : "=f"(v.x), "=f"(v.y) : "r"(sb + (u32)(r * 256 + kq * 8)));
            *(u32*)(sm + PJ_XH + sw128((u32)(r * 128 + kq * 4))) = packf16(v.x, v.y);
        }
        __syncthreads();

        u32 aF[4][4];
        #pragma unroll
        for (int kk = 0; kk < 4; kk++)
            ldsm4(frag_addr(smb + PJ_XH, mb, kk * 32),
                  aF[kk][0], aF[kk][1], aF[kk][2], aF[kk][3]);
        const u32 wb = sb + 16384u;
        #pragma unroll
        for (int nb = 0; nb < 6; nb++) {
            float* a0 = acc[2 * nb];
            float* a1 = acc[2 * nb + 1];
            #pragma unroll
            for (int kk = 0; kk < 4; kk++) {
                u32 b0, b1, b2, b3;
                ldsm4(frag_addr(wb, nh * 96 + nb * 16, kk * 32), b0, b1, b2, b3);
                mmah(a0, aF[kk][0], aF[kk][1], aF[kk][2], aF[kk][3], b0, b2);
                mmah(a1, aF[kk][0], aF[kk][1], aF[kk][2], aF[kk][3], b1, b3);
            }
        }
        __syncthreads();
        if (c + 2 < 16) pj_copy_stage(smb, x, m0, c + 2, t);
    }

    // epilogue: bias; q/k/v single fp16 planes; swizzled tiles
    const int grow0 = m0 + mb + g;
    #pragma unroll
    for (int nf = 0; nf < 12; nf++) {
        int n = nh * 96 + nf * 8 + 2 * tg;
        int sel = n >> 6, nl = n & 63;
        const float* bias = (sel == 0) ? bq : (sel == 1) ? bk : bv;
        float b0 = bias[nl], b1 = bias[nl + 1];
        float v00 = acc[nf][0] + b0, v01 = acc[nf][1] + b1;
        float v10 = acc[nf][2] + b0, v11 = acc[nf][3] + b1;
        u16* plane = (sel == 0) ? g_qf : (sel == 1) ? g_kf : g_vf;
        #pragma unroll
        for (int half = 0; half < 2; half++) {
            int grow = grow0 + half * 8;
            float a = half ? v10 : v00, bb = half ? v11 : v01;
            size_t tb = (size_t)(grow >> 7) * TILE_BYTES;
            u32 off = sw128((u32)((grow & 127) * 128 + nl * 2));
            *(u32*)((char*)plane + tb + off) = packf16(a, bb);
        }
    }
}

// ============================ Attention kernel ============================
// CTA = (mt, b, s): 128 q rows, split-K half, 256 threads / 8 warps.
// Q/K/V/P all single fp16; S single-pass; PV single-pass. 3-stage cp.async
// ring. No-max softmax. Split-K combine fused: first finisher publishes
// partials; second finisher (atomic counter) merges with its register copy
// and writes the final normalized output.
#define ATQ      0
#define ATKV0    16384
#define AT_STAGE 32768                   // K 16KB + V 16KB
#define AT_SMEM  (16384 + 3 * AT_STAGE)  // 114688

__device__ __forceinline__ void copy_kv(u32 dst, int b, int kt, int t) {
    size_t tb = ((size_t)(b * 32 + kt)) * TILE_BYTES;
    copy_plane(dst,          (const char*)g_kf + tb, t);
    copy_plane(dst + 16384,  (const char*)g_vf + tb, t);
}

__global__ __launch_bounds__(256) void attn_kernel(float* __restrict__ out)
{
    extern __shared__ char sm[];
    __shared__ int s_old;
    const u32 smb = smem_u32(sm);
    const int t = threadIdx.x, w = t >> 5, lane = t & 31;
    const int g = lane >> 2, tg = lane & 3;
    const int gb = blockIdx.x;
    const int mt = 31 - (gb >> 3);       // heavy tiles first
    const int b  = (gb >> 1) & 3;
    const int s  = gb & 1;
    const int mb = 16 * w;
    const float scale = 1.0f / 32.0f;

    const int n_t = mt + 1;
    const int h   = (n_t + 1) >> 1;
    const int kt0 = s ? h : 0;
    const int cnt = s ? (n_t - h) : h;

    // prefetch up to 3 stages (Q rides with stage 0's group)
    if (cnt > 0) {
        size_t qb = ((size_t)(b * 32 + mt)) * TILE_BYTES;
        copy_plane(smb + ATQ, (const char*)g_qf + qb, t);
        copy_kv(smb + ATKV0, b, kt0, t);
        cp_commit();
        if (cnt > 1) { copy_kv(smb + ATKV0 + AT_STAGE, b, kt0 + 1, t); cp_commit(); }
        if (cnt > 2) { copy_kv(smb + ATKV0 + 2 * AT_STAGE, b, kt0 + 2, t); cp_commit(); }
    }

    u32 qF[4][4];
    float oacc[8][4];
    #pragma unroll
    for (int i = 0; i < 8; i++)
        #pragma unroll
        for (int e = 0; e < 4; e++) oacc[i][e] = 0.0f;
    float l0 = 0.0f, l1 = 0.0f;
    const int rowg0 = mt * 128 + mb + g, rowg1 = rowg0 + 8;

    int buf = 0;
    for (int i = 0; i < cnt; i++) {
        const int ahead = cnt - 1 - i;   // stages still in flight beyond i
        if (ahead >= 2)      asm volatile("cp.async.wait_group 2;" ::: "memory");
        else if (ahead == 1) asm volatile("cp.async.wait_group 1;" ::: "memory");
        else                 asm volatile("cp.async.wait_group 0;" ::: "memory");
        __syncthreads();

        if (i == 0) {
            #pragma unroll
            for (int kk = 0; kk < 4; kk++)
                ldsm4(frag_addr(smb + ATQ, mb, kk * 32),
                      qF[kk][0], qF[kk][1], qF[kk][2], qF[kk][3]);
        }
        const int kt = kt0 + i;
        const u32 kb = smb + ATKV0 + (u32)buf * AT_STAGE;

        // ---- S = Q K^T, single fp16 pass ----
        float sacc[16][4];
        #pragma unroll
        for (int q2 = 0; q2 < 16; q2++)
            #pragma unroll
            for (int e = 0; e < 4; e++) sacc[q2][e] = 0.0f;
        #pragma unroll
        for (int nb = 0; nb < 8; nb++) {
            #pragma unroll
            for (int kk = 0; kk < 4; kk++) {
                u32 b0, b1, b2, b3;
                ldsm4(frag_addr(kb, nb * 16, kk * 32), b0, b1, b2, b3);
                mmah(sacc[2*nb],   qF[kk][0], qF[kk][1], qF[kk][2], qF[kk][3], b0, b2);
                mmah(sacc[2*nb+1], qF[kk][0], qF[kk][1], qF[kk][2], qF[kk][3], b1, b3);
            }
        }

        // ---- exp (no max); mask only on diagonal tile ----
        if (kt == mt) {
            #pragma unroll
            for (int nf = 0; nf < 16; nf++) {
                int colb = kt * 128 + nf * 8 + 2 * tg;
                float p0 = (colb     <= rowg0) ? __expf(sacc[nf][0] * scale) : 0.0f;
                float p1 = (colb + 1 <= rowg0) ? __expf(sacc[nf][1] * scale) : 0.0f;
                float p2 = (colb     <= rowg1) ? __expf(sacc[nf][2] * scale) : 0.0f;
                float p3 = (colb + 1 <= rowg1) ? __expf(sacc[nf][3] * scale) : 0.0f;
                l0 += p0 + p1; l1 += p2 + p3;
                sacc[nf][0] = p0; sacc[nf][1] = p1; sacc[nf][2] = p2; sacc[nf][3] = p3;
            }
        } else {
            #pragma unroll
            for (int nf = 0; nf < 16; nf++) {
                float p0 = __expf(sacc[nf][0] * scale);
                float p1 = __expf(sacc[nf][1] * scale);
                float p2 = __expf(sacc[nf][2] * scale);
                float p3 = __expf(sacc[nf][3] * scale);
                l0 += p0 + p1; l1 += p2 + p3;
                sacc[nf][0] = p0; sacc[nf][1] = p1; sacc[nf][2] = p2; sacc[nf][3] = p3;
            }
        }

        // ---- O += P V (P single fp16 in regs; V single; 1 combo) ----
        #pragma unroll
        for (int kk = 0; kk < 8; kk++) {
            u32 ah[4];
            ah[0] = packf16(sacc[2*kk][0],   sacc[2*kk][1]);
            ah[1] = packf16(sacc[2*kk][2],   sacc[2*kk][3]);
            ah[2] = packf16(sacc[2*kk+1][0], sacc[2*kk+1][1]);
            ah[3] = packf16(sacc[2*kk+1][2], sacc[2*kk+1][3]);
            #pragma unroll
            for (int nb = 0; nb < 4; nb++) {
                u32 vh0, vh1, vh2, vh3;
                ldsm4t(frag_addr(kb + 16384, kk * 16, nb * 32), vh0, vh1, vh2, vh3);
                mmah(oacc[2*nb],   ah[0], ah[1], ah[2], ah[3], vh0, vh1);
                mmah(oacc[2*nb+1], ah[0], ah[1], ah[2], ah[3], vh2, vh3);
            }
        }

        __syncthreads();
        if (i + 3 < cnt) {
            copy_kv(smb + ATKV0 + (u32)buf * AT_STAGE, b, kt + 3, t);
            cp_commit();
        }
        buf = (buf + 1 == 3) ? 0 : buf + 1;
    }

    l0 += __shfl_xor_sync(0xffffffffu, l0, 1);
    l0 += __shfl_xor_sync(0xffffffffu, l0, 2);
    l1 += __shfl_xor_sync(0xffffffffu, l1, 1);
    l1 += __shfl_xor_sync(0xffffffffu, l1, 2);

    // ---- publish own partials ----
    const size_t gr0 = (size_t)b * SEQ + rowg0;
    const size_t gr1 = gr0 + 8;
    float* po = g_po[s];
    #pragma unroll
    for (int nf = 0; nf < 8; nf++) {
        int col = nf * 8 + 2 * tg;
        *(float2*)&po[gr0 * HEAD + col] = make_float2(oacc[nf][0], oacc[nf][1]);
        *(float2*)&po[gr1 * HEAD + col] = make_float2(oacc[nf][2], oacc[nf][3]);
    }
    if (tg == 0) {
        g_pl[s][gr0] = l0;
        g_pl[s][gr1] = l1;
    }
    __threadfence();
    __syncthreads();

    // ---- arrival counter; second finisher merges & writes output ----
    const int blk = (mt << 2) | b;
    if (t == 0) s_old = atomicAdd(&g_flag[blk], 1);
    __syncthreads();
    if (s_old == 1) {
        __threadfence();   // acquire: other CTA's partials now visible
        const float* po_o = g_po[1 - s];
        const float* pl_o = g_pl[1 - s];
        float inv0 = 1.0f / (l0 + pl_o[gr0]);
        float inv1 = 1.0f / (l1 + pl_o[gr1]);
        #pragma unroll
        for (int nf = 0; nf < 8; nf++) {
            int col = nf * 8 + 2 * tg;
            float2 q0 = *(const float2*)&po_o[gr0 * HEAD + col];
            float2 q1 = *(const float2*)&po_o[gr1 * HEAD + col];
            *(float2*)&out[gr0 * HEAD + col] =
                make_float2((oacc[nf][0] + q0.x) * inv0, (oacc[nf][1] + q0.y) * inv0);
            *(float2*)&out[gr1 * HEAD + col] =
                make_float2((oacc[nf][2] + q1.x) * inv1, (oacc[nf][3] + q1.y) * inv1);
        }
        if (t == 0) g_flag[blk] = 0;   // self-reset for next graph replay
    }
}

// ============================ Launch ============================
extern "C" void kernel_launch(void* const* d_in, const int* in_sizes, int n_in,
                              void* d_out, int out_size)
{
    const float* x  = (const float*)d_in[0];
    const float* Wq = (const float*)d_in[1];
    const float* bq = (const float*)d_in[2];
    const float* Wk = (const float*)d_in[3];
    const float* bk = (const float*)d_in[4];
    const float* Wv = (const float*)d_in[5];
    const float* bv = (const float*)d_in[6];
    float* out = (float*)d_out;
    (void)in_sizes; (void)n_in; (void)out_size;

    cudaFuncSetAttribute(proj_kernel, cudaFuncAttributeMaxDynamicSharedMemorySize, PJ_SMEM);
    cudaFuncSetAttribute(attn_kernel, cudaFuncAttributeMaxDynamicSharedMemorySize, AT_SMEM);

    wprep_kernel<<<48, 256>>>(Wq, Wk, Wv);
    proj_kernel<<<BT / 64, 256, PJ_SMEM>>>(bq, bk, bv, x);
    attn_kernel<<<256, 256, AT_SMEM>>>(out);
}

// round 15
// speedup vs baseline: 1.0922x; 1.0922x over previous
#include <cuda_runtime.h>
#include <cuda_fp16.h>

#define BATCH   4
#define SEQ     4096
#define DMODEL  1024
#define HEAD    64
#define BT      (BATCH * SEQ)
#define TILE_BYTES 16384   // one 128x64 fp16 plane tile, SW128 swizzled

typedef unsigned int u32;
typedef unsigned short u16;

// fp16 operand planes (attention-ready swizzled tile layout)
__device__ u16 g_qf[BT * HEAD];            // q single fp16
__device__ u16 g_kf[BT * HEAD];            // k single fp16
__device__ u16 g_vf[BT * HEAD];            // v single fp16
// W single fp16 plane: chunk c tile = 192 n-rows x 64 k, 24KB, n-major SW128
__device__ u16 g_wf[16 * 192 * HEAD];
// split-K partials
__device__ float g_po[2][BT * HEAD];
__device__ float g_pl[2][BT];

// ============================ helpers ============================
__device__ __forceinline__ u32 smem_u32(const void* p) {
    u32 a;
    asm("{ .reg .u64 t; cvta.to.shared.u64 t, %1; cvt.u32.u64 %0, t; }" : "=r"(a) : "l"(p));
    return a;
}
__device__ __forceinline__ u32 sw128(u32 off) { return off ^ ((off >> 3) & 0x70); }

__device__ __forceinline__ void ldsm4(u32 a, u32& r0, u32& r1, u32& r2, u32& r3) {
    asm volatile("ldmatrix.sync.aligned.m8n8.x4.shared.b16 {%0,%1,%2,%3}, [%4];"
                 : "=r"(r0), "=r"(r1), "=r"(r2), "=r"(r3) : "r"(a));
}
__device__ __forceinline__ void ldsm4t(u32 a, u32& r0, u32& r1, u32& r2, u32& r3) {
    asm volatile("ldmatrix.sync.aligned.m8n8.x4.trans.shared.b16 {%0,%1,%2,%3}, [%4];"
                 : "=r"(r0), "=r"(r1), "=r"(r2), "=r"(r3) : "r"(a));
}
// fp16 mma m16n8k16, fp32 accumulate
__device__ __forceinline__ void mmah(float* d, u32 a0, u32 a1, u32 a2, u32 a3,
                                     u32 b0, u32 b1) {
    asm volatile(
        "mma.sync.aligned.m16n8k16.row.col.f32.f16.f16.f32 "
        "{%0,%1,%2,%3},{%4,%5,%6,%7},{%8,%9},{%0,%1,%2,%3};"
        : "+f"(d[0]), "+f"(d[1]), "+f"(d[2]), "+f"(d[3])
        : "r"(a0), "r"(a1), "r"(a2), "r"(a3), "r"(b0), "r"(b1));
}
__device__ __forceinline__ u32 packf16(float a, float b) {
    __half2 h = __floats2half2_rn(a, b);
    return *reinterpret_cast<u32*>(&h);
}
__device__ __forceinline__ u32 frag_addr(u32 base, int row0, int colb) {
    int lane = threadIdx.x & 31;
    int tile = lane >> 3, l7 = lane & 7;
    int row = row0 + l7 + ((tile & 1) << 3);
    int col = colb + ((tile >> 1) << 4);
    return base + sw128((u32)(row * 128 + col));
}
__device__ __forceinline__ void cpa16(u32 dst, const void* src) {
    asm volatile("cp.async.cg.shared.global [%0], [%1], 16;" :: "r"(dst), "l"(src));
}
__device__ __forceinline__ void cp_commit() {
    asm volatile("cp.async.commit_group;" ::: "memory");
}
__device__ __forceinline__ void copy_plane(u32 dst, const char* src, int t) {
    #pragma unroll
    for (int j = 0; j < 4; j++)
        cpa16(dst + (u32)(t * 16 + j * 4096), src + t * 16 + j * 4096);
}

// ============================ W prepass ============================
// grid 384 = 3 sels x 16 chunks x 8 parts; one load/convert/store per thread.
__global__ __launch_bounds__(256) void wprep_kernel(
    const float* __restrict__ Wq, const float* __restrict__ Wk,
    const float* __restrict__ Wv)
{
    const int id = blockIdx.x;
    const int sel = id >> 7;             // 0..2
    const int rem = id & 127;
    const int c = rem >> 3;              // 0..15
    const int part = rem & 7;            // 0..7
    const float* W = (sel == 0) ? Wq : (sel == 1) ? Wk : Wv;
    const int k0 = c * 64;
    char* tp = (char*)g_wf + (size_t)c * (192 * 128);

    int idx = part * 256 + threadIdx.x;  // 0..2047 = 64 nl x 32 kq
    int kq = idx & 31, nl = idx >> 5;
    float w0 = W[(size_t)(k0 + 2 * kq)     * HEAD + nl];
    float w1 = W[(size_t)(k0 + 2 * kq + 1) * HEAD + nl];
    u32 off = sw128((u32)((sel * 64 + nl) * 128 + kq * 4));
    *(u32*)(tp + off) = packf16(w0, w1);
}

// ============================ Projection kernel ============================
#define PJ_STAGE 40960
#define PJ_XH    (2 * PJ_STAGE)       // 81920, 8KB converted x plane
#define PJ_SMEM  (PJ_XH + 8192)       // 90112

__device__ __forceinline__ void pj_copy_stage(u32 smb, const float* x, int m0,
                                              int c, int t) {
    const u32 base = smb + (u32)(c & 1) * PJ_STAGE;
    const int k0 = c * 64;
    #pragma unroll
    for (int j = 0; j < 4; j++) {
        int i = t + j * 256;             // 1024 x 16B = 16KB
        int r = i >> 4, cq = i & 15;
        cpa16(base + (u32)(r * 256 + cq * 16),
              &x[(size_t)(m0 + r) * DMODEL + k0 + cq * 4]);
    }
    const char* wsrc = (const char*)g_wf + (size_t)c * (192 * 128);
    #pragma unroll
    for (int j = 0; j < 6; j++) {
        int i = t + j * 256;             // 1536 x 16B = 24KB
        cpa16(base + 16384u + (u32)(i * 16), wsrc + i * 16);
    }
    cp_commit();
}

__global__ __launch_bounds__(256) void proj_kernel(
    const float* __restrict__ bq, const float* __restrict__ bk,
    const float* __restrict__ bv, const float* __restrict__ x)
{
    extern __shared__ char sm[];
    const u32 smb = smem_u32(sm);
    const int t = threadIdx.x, w = t >> 5, lane = t & 31;
    const int g = lane >> 2, tg = lane & 3;
    const int m0 = blockIdx.x * 64;
    const int mq = w & 3, nh = w >> 2;
    const int mb = mq * 16;

    float acc[12][4];
    #pragma unroll
    for (int i = 0; i < 12; i++)
        #pragma unroll
        for (int e = 0; e < 4; e++) acc[i][e] = 0.0f;

    pj_copy_stage(smb, x, m0, 0, t);
    pj_copy_stage(smb, x, m0, 1, t);

    for (int c = 0; c < 16; c++) {
        if (c + 1 < 16) asm volatile("cp.async.wait_group 1;" ::: "memory");
        else            asm volatile("cp.async.wait_group 0;" ::: "memory");
        __syncthreads();

        const u32 sb = smb + (u32)(c & 1) * PJ_STAGE;
        // convert x chunk fp32 -> fp16 plane (64 rows x 64 k)
        #pragma unroll
        for (int j = 0; j < 8; j++) {
            int idx = t + j * 256;       // 2048 pairs
            int r = idx >> 5, kq = idx & 31;
            float2 v;
            asm volatile("ld.shared.v2.f32 {%0,%1}, [%2];"
                         : "=f"(v.x), "=f"(v.y) : "r"(sb + (u32)(r * 256 + kq * 8)));
            *(u32*)(sm + PJ_XH + sw128((u32)(r * 128 + kq * 4))) = packf16(v.x, v.y);
        }
        __syncthreads();

        u32 aF[4][4];
        #pragma unroll
        for (int kk = 0; kk < 4; kk++)
            ldsm4(frag_addr(smb + PJ_XH, mb, kk * 32),
                  aF[kk][0], aF[kk][1], aF[kk][2], aF[kk][3]);
        const u32 wb = sb + 16384u;
        #pragma unroll
        for (int nb = 0; nb < 6; nb++) {
            float* a0 = acc[2 * nb];
            float* a1 = acc[2 * nb + 1];
            #pragma unroll
            for (int kk = 0; kk < 4; kk++) {
                u32 b0, b1, b2, b3;
                ldsm4(frag_addr(wb, nh * 96 + nb * 16, kk * 32), b0, b1, b2, b3);
                mmah(a0, aF[kk][0], aF[kk][1], aF[kk][2], aF[kk][3], b0, b2);
                mmah(a1, aF[kk][0], aF[kk][1], aF[kk][2], aF[kk][3], b1, b3);
            }
        }
        __syncthreads();
        if (c + 2 < 16) pj_copy_stage(smb, x, m0, c + 2, t);
    }

    // epilogue: bias; q/k/v single fp16 planes; swizzled tiles
    const int grow0 = m0 + mb + g;
    #pragma unroll
    for (int nf = 0; nf < 12; nf++) {
        int n = nh * 96 + nf * 8 + 2 * tg;
        int sel = n >> 6, nl = n & 63;
        const float* bias = (sel == 0) ? bq : (sel == 1) ? bk : bv;
        float b0 = bias[nl], b1 = bias[nl + 1];
        float v00 = acc[nf][0] + b0, v01 = acc[nf][1] + b1;
        float v10 = acc[nf][2] + b0, v11 = acc[nf][3] + b1;
        u16* plane = (sel == 0) ? g_qf : (sel == 1) ? g_kf : g_vf;
        #pragma unroll
        for (int half = 0; half < 2; half++) {
            int grow = grow0 + half * 8;
            float a = half ? v10 : v00, bb = half ? v11 : v01;
            size_t tb = (size_t)(grow >> 7) * TILE_BYTES;
            u32 off = sw128((u32)((grow & 127) * 128 + nl * 2));
            *(u32*)((char*)plane + tb + off) = packf16(a, bb);
        }
    }
}

// ============================ Attention kernel ============================
// CTA = (mt, b, s): 128 q rows, split-K half, 256 threads / 8 warps.
// Q/K/V/P all single fp16; S single-pass; PV single-pass. 3-stage cp.async
// ring. No-max softmax; partials to gmem.
#define ATQ      0
#define ATKV0    16384
#define AT_STAGE 32768                   // K 16KB + V 16KB
#define AT_SMEM  (16384 + 3 * AT_STAGE)  // 114688

__device__ __forceinline__ void copy_kv(u32 dst, int b, int kt, int t) {
    size_t tb = ((size_t)(b * 32 + kt)) * TILE_BYTES;
    copy_plane(dst,          (const char*)g_kf + tb, t);
    copy_plane(dst + 16384,  (const char*)g_vf + tb, t);
}

__global__ __launch_bounds__(256) void attn_kernel()
{
    extern __shared__ char sm[];
    const u32 smb = smem_u32(sm);
    const int t = threadIdx.x, w = t >> 5, lane = t & 31;
    const int g = lane >> 2, tg = lane & 3;
    const int gb = blockIdx.x;
    const int mt = 31 - (gb >> 3);       // heavy tiles first
    const int b  = (gb >> 1) & 3;
    const int s  = gb & 1;
    const int mb = 16 * w;
    const float scale = 1.0f / 32.0f;

    const int n_t = mt + 1;
    const int h   = (n_t + 1) >> 1;
    const int kt0 = s ? h : 0;
    const int cnt = s ? (n_t - h) : h;

    // prefetch up to 3 stages (Q rides with stage 0's group)
    if (cnt > 0) {
        size_t qb = ((size_t)(b * 32 + mt)) * TILE_BYTES;
        copy_plane(smb + ATQ, (const char*)g_qf + qb, t);
        copy_kv(smb + ATKV0, b, kt0, t);
        cp_commit();
        if (cnt > 1) { copy_kv(smb + ATKV0 + AT_STAGE, b, kt0 + 1, t); cp_commit(); }
        if (cnt > 2) { copy_kv(smb + ATKV0 + 2 * AT_STAGE, b, kt0 + 2, t); cp_commit(); }
    }

    u32 qF[4][4];
    float oacc[8][4];
    #pragma unroll
    for (int i = 0; i < 8; i++)
        #pragma unroll
        for (int e = 0; e < 4; e++) oacc[i][e] = 0.0f;
    float l0 = 0.0f, l1 = 0.0f;
    const int rowg0 = mt * 128 + mb + g, rowg1 = rowg0 + 8;

    int buf = 0;
    for (int i = 0; i < cnt; i++) {
        const int ahead = cnt - 1 - i;   // stages still in flight beyond i
        if (ahead >= 2)      asm volatile("cp.async.wait_group 2;" ::: "memory");
        else if (ahead == 1) asm volatile("cp.async.wait_group 1;" ::: "memory");
        else                 asm volatile("cp.async.wait_group 0;" ::: "memory");
        __syncthreads();

        if (i == 0) {
            #pragma unroll
            for (int kk = 0; kk < 4; kk++)
                ldsm4(frag_addr(smb + ATQ, mb, kk * 32),
                      qF[kk][0], qF[kk][1], qF[kk][2], qF[kk][3]);
        }
        const int kt = kt0 + i;
        const u32 kb = smb + ATKV0 + (u32)buf * AT_STAGE;

        // ---- S = Q K^T, single fp16 pass ----
        float sacc[16][4];
        #pragma unroll
        for (int q2 = 0; q2 < 16; q2++)
            #pragma unroll
            for (int e = 0; e < 4; e++) sacc[q2][e] = 0.0f;
        #pragma unroll
        for (int nb = 0; nb < 8; nb++) {
            #pragma unroll
            for (int kk = 0; kk < 4; kk++) {
                u32 b0, b1, b2, b3;
                ldsm4(frag_addr(kb, nb * 16, kk * 32), b0, b1, b2, b3);
                mmah(sacc[2*nb],   qF[kk][0], qF[kk][1], qF[kk][2], qF[kk][3], b0, b2);
                mmah(sacc[2*nb+1], qF[kk][0], qF[kk][1], qF[kk][2], qF[kk][3], b1, b3);
            }
        }

        // ---- exp (no max); mask only on diagonal tile ----
        if (kt == mt) {
            #pragma unroll
            for (int nf = 0; nf < 16; nf++) {
                int colb = kt * 128 + nf * 8 + 2 * tg;
                float p0 = (colb     <= rowg0) ? __expf(sacc[nf][0] * scale) : 0.0f;
                float p1 = (colb + 1 <= rowg0) ? __expf(sacc[nf][1] * scale) : 0.0f;
                float p2 = (colb     <= rowg1) ? __expf(sacc[nf][2] * scale) : 0.0f;
                float p3 = (colb + 1 <= rowg1) ? __expf(sacc[nf][3] * scale) : 0.0f;
                l0 += p0 + p1; l1 += p2 + p3;
                sacc[nf][0] = p0; sacc[nf][1] = p1; sacc[nf][2] = p2; sacc[nf][3] = p3;
            }
        } else {
            #pragma unroll
            for (int nf = 0; nf < 16; nf++) {
                float p0 = __expf(sacc[nf][0] * scale);
                float p1 = __expf(sacc[nf][1] * scale);
                float p2 = __expf(sacc[nf][2] * scale);
                float p3 = __expf(sacc[nf][3] * scale);
                l0 += p0 + p1; l1 += p2 + p3;
                sacc[nf][0] = p0; sacc[nf][1] = p1; sacc[nf][2] = p2; sacc[nf][3] = p3;
            }
        }

        // ---- O += P V (P single fp16 in regs; V single; 1 combo) ----
        #pragma unroll
        for (int kk = 0; kk < 8; kk++) {
            u32 ah[4];
            ah[0] = packf16(sacc[2*kk][0],   sacc[2*kk][1]);
            ah[1] = packf16(sacc[2*kk][2],   sacc[2*kk][3]);
            ah[2] = packf16(sacc[2*kk+1][0], sacc[2*kk+1][1]);
            ah[3] = packf16(sacc[2*kk+1][2], sacc[2*kk+1][3]);
            #pragma unroll
            for (int nb = 0; nb < 4; nb++) {
                u32 vh0, vh1, vh2, vh3;
                ldsm4t(frag_addr(kb + 16384, kk * 16, nb * 32), vh0, vh1, vh2, vh3);
                mmah(oacc[2*nb],   ah[0], ah[1], ah[2], ah[3], vh0, vh1);
                mmah(oacc[2*nb+1], ah[0], ah[1], ah[2], ah[3], vh2, vh3);
            }
        }

        __syncthreads();
        if (i + 3 < cnt) {
            copy_kv(smb + ATKV0 + (u32)buf * AT_STAGE, b, kt + 3, t);
            cp_commit();
        }
        buf = (buf + 1 == 3) ? 0 : buf + 1;
    }

    l0 += __shfl_xor_sync(0xffffffffu, l0, 1);
    l0 += __shfl_xor_sync(0xffffffffu, l0, 2);
    l1 += __shfl_xor_sync(0xffffffffu, l1, 1);
    l1 += __shfl_xor_sync(0xffffffffu, l1, 2);

    const size_t gr0 = (size_t)b * SEQ + rowg0;
    const size_t gr1 = gr0 + 8;
    float* po = g_po[s];
    #pragma unroll
    for (int nf = 0; nf < 8; nf++) {
        int col = nf * 8 + 2 * tg;
        *(float2*)&po[gr0 * HEAD + col] = make_float2(oacc[nf][0], oacc[nf][1]);
        *(float2*)&po[gr1 * HEAD + col] = make_float2(oacc[nf][2], oacc[nf][3]);
    }
    if (tg == 0) {
        g_pl[s][gr0] = l0;
        g_pl[s][gr1] = l1;
    }
}

// ============================ Combine kernel ============================
__global__ __launch_bounds__(256) void combine_kernel(float* __restrict__ out)
{
    int idx = blockIdx.x * 256 + threadIdx.x;
    float4 a = ((const float4*)g_po[0])[idx];
    float4 c = ((const float4*)g_po[1])[idx];
    int row = idx >> 4;
    float inv = 1.0f / (g_pl[0][row] + g_pl[1][row]);
    float4 r;
    r.x = (a.x + c.x) * inv;
    r.y = (a.y + c.y) * inv;
    r.z = (a.z + c.z) * inv;
    r.w = (a.w + c.w) * inv;
    ((float4*)out)[idx] = r;
}

// ============================ Launch ============================
extern "C" void kernel_launch(void* const* d_in, const int* in_sizes, int n_in,
                              void* d_out, int out_size)
{
    const float* x  = (const float*)d_in[0];
    const float* Wq = (const float*)d_in[1];
    const float* bq = (const float*)d_in[2];
    const float* Wk = (const float*)d_in[3];
    const float* bk = (const float*)d_in[4];
    const float* Wv = (const float*)d_in[5];
    const float* bv = (const float*)d_in[6];
    float* out = (float*)d_out;
    (void)in_sizes; (void)n_in; (void)out_size;

    cudaFuncSetAttribute(proj_kernel, cudaFuncAttributeMaxDynamicSharedMemorySize, PJ_SMEM);
    cudaFuncSetAttribute(attn_kernel, cudaFuncAttributeMaxDynamicSharedMemorySize, AT_SMEM);

    wprep_kernel<<<384, 256>>>(Wq, Wk, Wv);
    proj_kernel<<<BT / 64, 256, PJ_SMEM>>>(bq, bk, bv, x);
    attn_kernel<<<256, 256, AT_SMEM>>>();
    combine_kernel<<<BT * HEAD / 4 / 256, 256>>>(out);
}

// round 16
// speedup vs baseline: 1.0946x; 1.0022x over previous
#include <cuda_runtime.h>
#include <cuda_fp16.h>

#define BATCH   4
#define SEQ     4096
#define DMODEL  1024
#define HEAD    64
#define BT      (BATCH * SEQ)
#define TILE_BYTES 16384   // one 128x64 fp16 plane tile, SW128 swizzled

typedef unsigned int u32;
typedef unsigned short u16;

// fp16 operand planes (attention-ready swizzled tile layout)
__device__ u16 g_qf[BT * HEAD];            // q single fp16
__device__ u16 g_kf[BT * HEAD];            // k single fp16
__device__ u16 g_vf[BT * HEAD];            // v single fp16
// W single fp16 plane: chunk c tile = 192 n-rows x 64 k, 24KB, n-major SW128
__device__ u16 g_wf[16 * 192 * HEAD];
// split-K partials (4-way)
__device__ float g_po[4][BT * HEAD];
__device__ float g_pl[4][BT];

// ============================ helpers ============================
__device__ __forceinline__ u32 smem_u32(const void* p) {
    u32 a;
    asm("{ .reg .u64 t; cvta.to.shared.u64 t, %1; cvt.u32.u64 %0, t; }" : "=r"(a) : "l"(p));
    return a;
}
__device__ __forceinline__ u32 sw128(u32 off) { return off ^ ((off >> 3) & 0x70); }

__device__ __forceinline__ void ldsm4(u32 a, u32& r0, u32& r1, u32& r2, u32& r3) {
    asm volatile("ldmatrix.sync.aligned.m8n8.x4.shared.b16 {%0,%1,%2,%3}, [%4];"
                 : "=r"(r0), "=r"(r1), "=r"(r2), "=r"(r3) : "r"(a));
}
__device__ __forceinline__ void ldsm4t(u32 a, u32& r0, u32& r1, u32& r2, u32& r3) {
    asm volatile("ldmatrix.sync.aligned.m8n8.x4.trans.shared.b16 {%0,%1,%2,%3}, [%4];"
                 : "=r"(r0), "=r"(r1), "=r"(r2), "=r"(r3) : "r"(a));
}
// fp16 mma m16n8k16, fp32 accumulate
__device__ __forceinline__ void mmah(float* d, u32 a0, u32 a1, u32 a2, u32 a3,
                                     u32 b0, u32 b1) {
    asm volatile(
        "mma.sync.aligned.m16n8k16.row.col.f32.f16.f16.f32 "
        "{%0,%1,%2,%3},{%4,%5,%6,%7},{%8,%9},{%0,%1,%2,%3};"
        : "+f"(d[0]), "+f"(d[1]), "+f"(d[2]), "+f"(d[3])
        : "r"(a0), "r"(a1), "r"(a2), "r"(a3), "r"(b0), "r"(b1));
}
__device__ __forceinline__ u32 packf16(float a, float b) {
    __half2 h = __floats2half2_rn(a, b);
    return *reinterpret_cast<u32*>(&h);
}
__device__ __forceinline__ u32 frag_addr(u32 base, int row0, int colb) {
    int lane = threadIdx.x & 31;
    int tile = lane >> 3, l7 = lane & 7;
    int row = row0 + l7 + ((tile & 1) << 3);
    int col = colb + ((tile >> 1) << 4);
    return base + sw128((u32)(row * 128 + col));
}
__device__ __forceinline__ void cpa16(u32 dst, const void* src) {
    asm volatile("cp.async.cg.shared.global [%0], [%1], 16;" :: "r"(dst), "l"(src));
}
__device__ __forceinline__ void cp_commit() {
    asm volatile("cp.async.commit_group;" ::: "memory");
}
__device__ __forceinline__ void copy_plane(u32 dst, const char* src, int t) {
    #pragma unroll
    for (int j = 0; j < 4; j++)
        cpa16(dst + (u32)(t * 16 + j * 4096), src + t * 16 + j * 4096);
}
// 8KB half-plane copy (64-row tile)
__device__ __forceinline__ void copy_half(u32 dst, const char* src, int t) {
    #pragma unroll
    for (int j = 0; j < 2; j++)
        cpa16(dst + (u32)(t * 16 + j * 4096), src + t * 16 + j * 4096);
}

// ============================ W prepass ============================
// grid 384 = 3 sels x 16 chunks x 8 parts; one load/convert/store per thread.
__global__ __launch_bounds__(256) void wprep_kernel(
    const float* __restrict__ Wq, const float* __restrict__ Wk,
    const float* __restrict__ Wv)
{
    const int id = blockIdx.x;
    const int sel = id >> 7;
    const int rem = id & 127;
    const int c = rem >> 3;
    const int part = rem & 7;
    const float* W = (sel == 0) ? Wq : (sel == 1) ? Wk : Wv;
    const int k0 = c * 64;
    char* tp = (char*)g_wf + (size_t)c * (192 * 128);

    int idx = part * 256 + threadIdx.x;
    int kq = idx & 31, nl = idx >> 5;
    float w0 = W[(size_t)(k0 + 2 * kq)     * HEAD + nl];
    float w1 = W[(size_t)(k0 + 2 * kq + 1) * HEAD + nl];
    u32 off = sw128((u32)((sel * 64 + nl) * 128 + kq * 4));
    *(u32*)(tp + off) = packf16(w0, w1);
}

// ============================ Projection kernel ============================
#define PJ_STAGE 40960
#define PJ_XH    (2 * PJ_STAGE)       // 81920, 8KB converted x plane
#define PJ_SMEM  (PJ_XH + 8192)       // 90112

__device__ __forceinline__ void pj_copy_stage(u32 smb, const float* x, int m0,
                                              int c, int t) {
    const u32 base = smb + (u32)(c & 1) * PJ_STAGE;
    const int k0 = c * 64;
    #pragma unroll
    for (int j = 0; j < 4; j++) {
        int i = t + j * 256;
        int r = i >> 4, cq = i & 15;
        cpa16(base + (u32)(r * 256 + cq * 16),
              &x[(size_t)(m0 + r) * DMODEL + k0 + cq * 4]);
    }
    const char* wsrc = (const char*)g_wf + (size_t)c * (192 * 128);
    #pragma unroll
    for (int j = 0; j < 6; j++) {
        int i = t + j * 256;
        cpa16(base + 16384u + (u32)(i * 16), wsrc + i * 16);
    }
    cp_commit();
}

__global__ __launch_bounds__(256) void proj_kernel(
    const float* __restrict__ bq, const float* __restrict__ bk,
    const float* __restrict__ bv, const float* __restrict__ x)
{
    extern __shared__ char sm[];
    const u32 smb = smem_u32(sm);
    const int t = threadIdx.x, w = t >> 5, lane = t & 31;
    const int g = lane >> 2, tg = lane & 3;
    const int m0 = blockIdx.x * 64;
    const int mq = w & 3, nh = w >> 2;
    const int mb = mq * 16;

    float acc[12][4];
    #pragma unroll
    for (int i = 0; i < 12; i++)
        #pragma unroll
        for (int e = 0; e < 4; e++) acc[i][e] = 0.0f;

    pj_copy_stage(smb, x, m0, 0, t);
    pj_copy_stage(smb, x, m0, 1, t);

    for (int c = 0; c < 16; c++) {
        if (c + 1 < 16) asm volatile("cp.async.wait_group 1;" ::: "memory");
        else            asm volatile("cp.async.wait_group 0;" ::: "memory");
        __syncthreads();

        const u32 sb = smb + (u32)(c & 1) * PJ_STAGE;
        #pragma unroll
        for (int j = 0; j < 8; j++) {
            int idx = t + j * 256;
            int r = idx >> 5, kq = idx & 31;
            float2 v;
            asm volatile("ld.shared.v2.f32 {%0,%1}, [%2];"
                         : "=f"(v.x), "=f"(v.y) : "r"(sb + (u32)(r * 256 + kq * 8)));
            *(u32*)(sm + PJ_XH + sw128((u32)(r * 128 + kq * 4))) = packf16(v.x, v.y);
        }
        __syncthreads();

        u32 aF[4][4];
        #pragma unroll
        for (int kk = 0; kk < 4; kk++)
            ldsm4(frag_addr(smb + PJ_XH, mb, kk * 32),
                  aF[kk][0], aF[kk][1], aF[kk][2], aF[kk][3]);
        const u32 wb = sb + 16384u;
        #pragma unroll
        for (int nb = 0; nb < 6; nb++) {
            float* a0 = acc[2 * nb];
            float* a1 = acc[2 * nb + 1];
            #pragma unroll
            for (int kk = 0; kk < 4; kk++) {
                u32 b0, b1, b2, b3;
                ldsm4(frag_addr(wb, nh * 96 + nb * 16, kk * 32), b0, b1, b2, b3);
                mmah(a0, aF[kk][0], aF[kk][1], aF[kk][2], aF[kk][3], b0, b2);
                mmah(a1, aF[kk][0], aF[kk][1], aF[kk][2], aF[kk][3], b1, b3);
            }
        }
        __syncthreads();
        if (c + 2 < 16) pj_copy_stage(smb, x, m0, c + 2, t);
    }

    // epilogue: bias; q/k/v single fp16 planes; swizzled tiles
    const int grow0 = m0 + mb + g;
    #pragma unroll
    for (int nf = 0; nf < 12; nf++) {
        int n = nh * 96 + nf * 8 + 2 * tg;
        int sel = n >> 6, nl = n & 63;
        const float* bias = (sel == 0) ? bq : (sel == 1) ? bk : bv;
        float b0 = bias[nl], b1 = bias[nl + 1];
        float v00 = acc[nf][0] + b0, v01 = acc[nf][1] + b1;
        float v10 = acc[nf][2] + b0, v11 = acc[nf][3] + b1;
        u16* plane = (sel == 0) ? g_qf : (sel == 1) ? g_kf : g_vf;
        #pragma unroll
        for (int half = 0; half < 2; half++) {
            int grow = grow0 + half * 8;
            float a = half ? v10 : v00, bb = half ? v11 : v01;
            size_t tb = (size_t)(grow >> 7) * TILE_BYTES;
            u32 off = sw128((u32)((grow & 127) * 128 + nl * 2));
            *(u32*)((char*)plane + tb + off) = packf16(a, bb);
        }
    }
}

// ============================ Attention kernel ============================
// CTA = (mt, b, s): 128 q rows, split-K quarter over 64-key tiles.
// 256 threads / 8 warps, 2 CTAs/SM (48KB smem, <=128 regs).
// Q/K/V/P single fp16; S single-pass; PV single-pass; 2-stage cp.async ring.
#define ATQ      0
#define ATKV0    16384
#define AT_STAGE 16384                   // K 8KB + V 8KB
#define AT_SMEM  (16384 + 2 * AT_STAGE)  // 49152

__device__ __forceinline__ void copy_kv64(u32 dst, int b, int kt, int t) {
    size_t tb = ((size_t)(b * 32 + (kt >> 1))) * TILE_BYTES
              + (size_t)(kt & 1) * 8192;
    copy_half(dst,        (const char*)g_kf + tb, t);
    copy_half(dst + 8192, (const char*)g_vf + tb, t);
}

__global__ __launch_bounds__(256, 2) void attn_kernel()
{
    extern __shared__ char sm[];
    const u32 smb = smem_u32(sm);
    const int t = threadIdx.x, w = t >> 5, lane = t & 31;
    const int g = lane >> 2, tg = lane & 3;
    const int gb = blockIdx.x;
    const int mt = 31 - (gb >> 4);       // heavy tiles first
    const int b  = (gb >> 2) & 3;
    const int s  = gb & 3;
    const int mb = 16 * w;
    const float scale = 1.0f / 32.0f;

    // 64-key tiles: n_t = 2*mt + 2, split 4 ways
    const int n_t = 2 * mt + 2;
    const int q4  = n_t >> 2, r4 = n_t & 3;
    const int cnt = q4 + (s < r4 ? 1 : 0);
    const int kt0 = s * q4 + (s < r4 ? s : r4);

    if (cnt > 0) {
        size_t qb = ((size_t)(b * 32 + mt)) * TILE_BYTES;
        copy_plane(smb + ATQ, (const char*)g_qf + qb, t);
        copy_kv64(smb + ATKV0, b, kt0, t);
        cp_commit();
        if (cnt > 1) { copy_kv64(smb + ATKV0 + AT_STAGE, b, kt0 + 1, t); cp_commit(); }
    }

    u32 qF[4][4];
    float oacc[8][4];
    #pragma unroll
    for (int i = 0; i < 8; i++)
        #pragma unroll
        for (int e = 0; e < 4; e++) oacc[i][e] = 0.0f;
    float l0 = 0.0f, l1 = 0.0f;
    const int rowg0 = mt * 128 + mb + g, rowg1 = rowg0 + 8;

    for (int i = 0; i < cnt; i++) {
        if (i + 1 < cnt) asm volatile("cp.async.wait_group 1;" ::: "memory");
        else             asm volatile("cp.async.wait_group 0;" ::: "memory");
        __syncthreads();

        if (i == 0) {
            #pragma unroll
            for (int kk = 0; kk < 4; kk++)
                ldsm4(frag_addr(smb + ATQ, mb, kk * 32),
                      qF[kk][0], qF[kk][1], qF[kk][2], qF[kk][3]);
        }
        const int kt = kt0 + i;
        const u32 kb = smb + ATKV0 + (u32)(i & 1) * AT_STAGE;

        // ---- S = Q K^T over 64 keys, single fp16 pass ----
        float sacc[8][4];
        #pragma unroll
        for (int q2 = 0; q2 < 8; q2++)
            #pragma unroll
            for (int e = 0; e < 4; e++) sacc[q2][e] = 0.0f;
        #pragma unroll
        for (int nb = 0; nb < 4; nb++) {
            #pragma unroll
            for (int kk = 0; kk < 4; kk++) {
                u32 b0, b1, b2, b3;
                ldsm4(frag_addr(kb, nb * 16, kk * 32), b0, b1, b2, b3);
                mmah(sacc[2*nb],   qF[kk][0], qF[kk][1], qF[kk][2], qF[kk][3], b0, b2);
                mmah(sacc[2*nb+1], qF[kk][0], qF[kk][1], qF[kk][2], qF[kk][3], b1, b3);
            }
        }

        // ---- exp (no max); mask only on diagonal-touching tiles ----
        if (kt >= 2 * mt) {
            #pragma unroll
            for (int nf = 0; nf < 8; nf++) {
                int colb = kt * 64 + nf * 8 + 2 * tg;
                float p0 = (colb     <= rowg0) ? __expf(sacc[nf][0] * scale) : 0.0f;
                float p1 = (colb + 1 <= rowg0) ? __expf(sacc[nf][1] * scale) : 0.0f;
                float p2 = (colb     <= rowg1) ? __expf(sacc[nf][2] * scale) : 0.0f;
                float p3 = (colb + 1 <= rowg1) ? __expf(sacc[nf][3] * scale) : 0.0f;
                l0 += p0 + p1; l1 += p2 + p3;
                sacc[nf][0] = p0; sacc[nf][1] = p1; sacc[nf][2] = p2; sacc[nf][3] = p3;
            }
        } else {
            #pragma unroll
            for (int nf = 0; nf < 8; nf++) {
                float p0 = __expf(sacc[nf][0] * scale);
                float p1 = __expf(sacc[nf][1] * scale);
                float p2 = __expf(sacc[nf][2] * scale);
                float p3 = __expf(sacc[nf][3] * scale);
                l0 += p0 + p1; l1 += p2 + p3;
                sacc[nf][0] = p0; sacc[nf][1] = p1; sacc[nf][2] = p2; sacc[nf][3] = p3;
            }
        }

        // ---- O += P V over this 64-key tile (P fp16 in regs; 1 combo) ----
        #pragma unroll
        for (int kk = 0; kk < 4; kk++) {
            u32 ah[4];
            ah[0] = packf16(sacc[2*kk][0],   sacc[2*kk][1]);
            ah[1] = packf16(sacc[2*kk][2],   sacc[2*kk][3]);
            ah[2] = packf16(sacc[2*kk+1][0], sacc[2*kk+1][1]);
            ah[3] = packf16(sacc[2*kk+1][2], sacc[2*kk+1][3]);
            #pragma unroll
            for (int nb = 0; nb < 4; nb++) {
                u32 vh0, vh1, vh2, vh3;
                ldsm4t(frag_addr(kb + 8192, kk * 16, nb * 32), vh0, vh1, vh2, vh3);
                mmah(oacc[2*nb],   ah[0], ah[1], ah[2], ah[3], vh0, vh1);
                mmah(oacc[2*nb+1], ah[0], ah[1], ah[2], ah[3], vh2, vh3);
            }
        }

        __syncthreads();
        if (i + 2 < cnt) {
            copy_kv64(smb + ATKV0 + (u32)(i & 1) * AT_STAGE, b, kt + 2, t);
            cp_commit();
        }
    }

    l0 += __shfl_xor_sync(0xffffffffu, l0, 1);
    l0 += __shfl_xor_sync(0xffffffffu, l0, 2);
    l1 += __shfl_xor_sync(0xffffffffu, l1, 1);
    l1 += __shfl_xor_sync(0xffffffffu, l1, 2);

    const size_t gr0 = (size_t)b * SEQ + rowg0;
    const size_t gr1 = gr0 + 8;
    float* po = g_po[s];
    #pragma unroll
    for (int nf = 0; nf < 8; nf++) {
        int col = nf * 8 + 2 * tg;
        *(float2*)&po[gr0 * HEAD + col] = make_float2(oacc[nf][0], oacc[nf][1]);
        *(float2*)&po[gr1 * HEAD + col] = make_float2(oacc[nf][2], oacc[nf][3]);
    }
    if (tg == 0) {
        g_pl[s][gr0] = l0;
        g_pl[s][gr1] = l1;
    }
}

// ============================ Combine kernel ============================
__global__ __launch_bounds__(256) void combine_kernel(float* __restrict__ out)
{
    int idx = blockIdx.x * 256 + threadIdx.x;
    int row = idx >> 4;
    float4 a = ((const float4*)g_po[0])[idx];
    float4 c = ((const float4*)g_po[1])[idx];
    float4 d = ((const float4*)g_po[2])[idx];
    float4 e = ((const float4*)g_po[3])[idx];
    float inv = 1.0f / (g_pl[0][row] + g_pl[1][row] + g_pl[2][row] + g_pl[3][row]);
    float4 r;
    r.x = (a.x + c.x + d.x + e.x) * inv;
    r.y = (a.y + c.y + d.y + e.y) * inv;
    r.z = (a.z + c.z + d.z + e.z) * inv;
    r.w = (a.w + c.w + d.w + e.w) * inv;
    ((float4*)out)[idx] = r;
}

// ============================ Launch ============================
extern "C" void kernel_launch(void* const* d_in, const int* in_sizes, int n_in,
                              void* d_out, int out_size)
{
    const float* x  = (const float*)d_in[0];
    const float* Wq = (const float*)d_in[1];
    const float* bq = (const float*)d_in[2];
    const float* Wk = (const float*)d_in[3];
    const float* bk = (const float*)d_in[4];
    const float* Wv = (const float*)d_in[5];
    const float* bv = (const float*)d_in[6];
    float* out = (float*)d_out;
    (void)in_sizes; (void)n_in; (void)out_size;

    cudaFuncSetAttribute(proj_kernel, cudaFuncAttributeMaxDynamicSharedMemorySize, PJ_SMEM);
    cudaFuncSetAttribute(attn_kernel, cudaFuncAttributeMaxDynamicSharedMemorySize, AT_SMEM);

    wprep_kernel<<<384, 256>>>(Wq, Wk, Wv);
    proj_kernel<<<BT / 64, 256, PJ_SMEM>>>(bq, bk, bv, x);
    attn_kernel<<<512, 256, AT_SMEM>>>();
    combine_kernel<<<BT * HEAD / 4 / 256, 256>>>(out);
}